// round 13
// baseline (speedup 1.0000x reference)
#include <cuda_runtime.h>
#include <cuda_bf16.h>
#include <math.h>

static constexpr int N_ROWS = 8192;
static constexpr int A_ART  = 32;
static constexpr int D_DIM  = 768;
static constexpr int O_DIM  = 256;
static constexpr float LN_EPS = 1e-5f;

// ---------------- GEMM geometry --------------------------------------------
static constexpr int CTA_M = 64;                    // rows per CTA
static constexpr int G_TILES = N_ROWS / CTA_M;      // 128 CTAs
static constexpr int KCH = 32;                      // k per chunk
static constexpr int NCH = D_DIM / KCH;             // 24 chunks
static constexpr int PITCH = 40;                    // bf16 per smem row (20 words)
static constexpr int A_SZ = CTA_M * PITCH * 2;      // 5120 B  per split
static constexpr int B_SZ = O_DIM * PITCH * 2;      // 20480 B per split
static constexpr int OFF_AH = 0;
static constexpr int OFF_AL = A_SZ;                 // 5120
static constexpr int OFF_BH = 2 * A_SZ;             // 10240
static constexpr int OFF_BL = 2 * A_SZ + B_SZ;      // 30720
static constexpr int STAGE  = 2 * (A_SZ + B_SZ);    // 51200
static constexpr int HPITCH = 260;                  // f32 epilogue tile pitch

// bf16 hi/lo operand planes (zero-init; cnt==0 rows never written -> bias-only h, masked)
__device__ unsigned short g_Ah[(size_t)N_ROWS * D_DIM];
__device__ unsigned short g_Al[(size_t)N_ROWS * D_DIM];
__device__ unsigned short g_Bh[(size_t)O_DIM * D_DIM];   // [n][k]
__device__ unsigned short g_Bl[(size_t)O_DIM * D_DIM];

// ---------------------------------------------------------------------------
__device__ __forceinline__ bool counts_is_i64(const int* __restrict__ cw) {
    bool i64 = true;
    #pragma unroll
    for (int i = 0; i < 32; ++i)
        if (cw[2 * i + 1] != 0) i64 = false;
    return i64;
}
__device__ __forceinline__ int load_count(const int* __restrict__ cw, bool i64, int n) {
    return i64 ? cw[2 * n] : cw[n];
}
__device__ __forceinline__ unsigned smem_u32(const void* p) {
    unsigned a;
    asm("{ .reg .u64 t; cvta.to.shared.u64 t, %1; cvt.u32.u64 %0, t; }"
        : "=r"(a) : "l"(p));
    return a;
}
__device__ __forceinline__ void cp16(unsigned dst, const void* src) {
    asm volatile("cp.async.cg.shared.global [%0], [%1], 16;" :: "r"(dst), "l"(src));
}
__device__ __forceinline__ void bf16_split(float x, unsigned short& h, unsigned short& l) {
    const __nv_bfloat16 hb = __float2bfloat16(x);
    h = __bfloat16_as_ushort(hb);
    l = __bfloat16_as_ushort(__float2bfloat16(x - __bfloat162float(hb)));
}

// ---------------------------------------------------------------------------
// Weight prep: tiled 32x32 transpose, grid (24, 8).
// ---------------------------------------------------------------------------
__global__ void __launch_bounds__(256) prep_w_kernel(const float* __restrict__ proj_w) {
    __shared__ float t[32][33];
    const int k0 = blockIdx.x * 32;
    const int n0 = blockIdx.y * 32;
    const int tid = threadIdx.x;
    const int lr = tid >> 5;          // 0..7
    const int lc = tid & 31;
    #pragma unroll
    for (int j = 0; j < 4; ++j)
        t[lr + 8 * j][lc] = proj_w[(size_t)(k0 + lr + 8 * j) * O_DIM + n0 + lc];
    __syncthreads();
    const int n  = tid >> 3;          // 0..31
    const int kq = tid & 7;           // 4 k each
    unsigned short hs[4], ls[4];
    #pragma unroll
    for (int i = 0; i < 4; ++i)
        bf16_split(t[kq * 4 + i][n], hs[i], ls[i]);
    const size_t base = (size_t)(n0 + n) * D_DIM + k0 + kq * 4;
    *reinterpret_cast<uint2*>(&g_Bh[base]) =
        make_uint2(hs[0] | (hs[1] << 16), hs[2] | (hs[3] << 16));
    *reinterpret_cast<uint2*>(&g_Bl[base]) =
        make_uint2(ls[0] | (ls[1] << 16), ls[2] | (ls[3] << 16));
}

// ---------------------------------------------------------------------------
// Kernel A: masked attention softmax pooling, ZERO staging.
// Phase 1 streams articles from GMEM for scores (the only DRAM read);
// phase 3 re-reads them L2-hot (working set ~30-40 MB << 126 MB L2).
// smem = 256 B -> occupancy register-bound, dense DRAM request stream.
// ---------------------------------------------------------------------------
__global__ void __launch_bounds__(256, 4) pool_kernel(
    const float* __restrict__ articles,
    const int*   __restrict__ counts_w,
    const float* __restrict__ attn_w,
    const float* __restrict__ attn_b)
{
    __shared__ float s_scores[A_ART];
    __shared__ float s_wt[A_ART];

    const bool i64 = counts_is_i64(counts_w);
    const int n = blockIdx.x;
    const int cnt = load_count(counts_w, i64, n);
    if (cnt <= 0) return;                     // gemm epilogue writes no_news

    const int tid  = threadIdx.x;
    const int wid  = tid >> 5;
    const int lane = tid & 31;

    const float4* src4 = reinterpret_cast<const float4*>(
        articles + (size_t)n * A_ART * D_DIM);
    const float4* aw4 = reinterpret_cast<const float4*>(attn_w);

    // ---- phase 1: scores, warp per article, streamed from GMEM ----
    for (int a = wid; a < cnt; a += 8) {
        const float4* v4 = src4 + a * (D_DIM / 4);
        float part = 0.f;
        #pragma unroll
        for (int j = 0; j < 6; ++j) {
            const int idx = lane + 32 * j;
            const float4 v = v4[idx];
            const float4 w = __ldg(aw4 + idx);
            part += v.x * w.x + v.y * w.y + v.z * w.z + v.w * w.w;
        }
        #pragma unroll
        for (int o = 16; o > 0; o >>= 1)
            part += __shfl_xor_sync(0xffffffffu, part, o);
        if (lane == 0) s_scores[a] = part;
    }
    __syncthreads();

    // ---- phase 2: softmax over valid articles (warp 0) ----
    if (wid == 0) {
        const float b = attn_b[0];
        float s = (lane < cnt) ? (s_scores[lane] + b) : -3.0e38f;
        float m = s;
        #pragma unroll
        for (int o = 16; o > 0; o >>= 1)
            m = fmaxf(m, __shfl_xor_sync(0xffffffffu, m, o));
        float e = (lane < cnt) ? expf(s - m) : 0.f;
        float sum = e;
        #pragma unroll
        for (int o = 16; o > 0; o >>= 1)
            sum += __shfl_xor_sync(0xffffffffu, sum, o);
        if (lane < cnt) s_wt[lane] = e / sum;
    }
    __syncthreads();

    // ---- phase 3: pooled[d] = sum_a w[a]*art[a][d], L2-hot re-read ----
    if (tid < D_DIM / 4) {
        float4 acc = make_float4(0.f, 0.f, 0.f, 0.f);
        int a = 0;
        for (; a + 4 <= cnt; a += 4) {        // MLP=4 independent loads
            const float4 v0 = src4[(a + 0) * (D_DIM / 4) + tid];
            const float4 v1 = src4[(a + 1) * (D_DIM / 4) + tid];
            const float4 v2 = src4[(a + 2) * (D_DIM / 4) + tid];
            const float4 v3 = src4[(a + 3) * (D_DIM / 4) + tid];
            const float w0 = s_wt[a], w1 = s_wt[a + 1];
            const float w2 = s_wt[a + 2], w3 = s_wt[a + 3];
            acc.x = fmaf(w0, v0.x, fmaf(w1, v1.x, fmaf(w2, v2.x, fmaf(w3, v3.x, acc.x))));
            acc.y = fmaf(w0, v0.y, fmaf(w1, v1.y, fmaf(w2, v2.y, fmaf(w3, v3.y, acc.y))));
            acc.z = fmaf(w0, v0.z, fmaf(w1, v1.z, fmaf(w2, v2.z, fmaf(w3, v3.z, acc.z))));
            acc.w = fmaf(w0, v0.w, fmaf(w1, v1.w, fmaf(w2, v2.w, fmaf(w3, v3.w, acc.w))));
        }
        for (; a < cnt; ++a) {
            const float wa = s_wt[a];
            const float4 v = src4[a * (D_DIM / 4) + tid];
            acc.x = fmaf(wa, v.x, acc.x);
            acc.y = fmaf(wa, v.y, acc.y);
            acc.z = fmaf(wa, v.z, acc.z);
            acc.w = fmaf(wa, v.w, acc.w);
        }
        unsigned short hs[4], ls[4];
        bf16_split(acc.x, hs[0], ls[0]);
        bf16_split(acc.y, hs[1], ls[1]);
        bf16_split(acc.z, hs[2], ls[2]);
        bf16_split(acc.w, hs[3], ls[3]);
        const size_t base = (size_t)n * D_DIM + tid * 4;
        *reinterpret_cast<uint2*>(&g_Ah[base]) =
            make_uint2(hs[0] | (hs[1] << 16), hs[2] | (hs[3] << 16));
        *reinterpret_cast<uint2*>(&g_Al[base]) =
            make_uint2(ls[0] | (ls[1] << 16), ls[2] | (ls[3] << 16));
    }
}

// ---------------------------------------------------------------------------
// Kernel B: bf16x3 GEMM (mma.sync.m16n8k16) with ldmatrix fragment loads and
// a 3-stage cp.async pipeline (one __syncthreads per chunk).
// ---------------------------------------------------------------------------
__device__ __forceinline__ void mma16816(float* c, const unsigned* a,
                                         unsigned b0, unsigned b1) {
    asm volatile(
        "mma.sync.aligned.m16n8k16.row.col.f32.bf16.bf16.f32 "
        "{%0,%1,%2,%3}, {%4,%5,%6,%7}, {%8,%9}, {%0,%1,%2,%3};"
        : "+f"(c[0]), "+f"(c[1]), "+f"(c[2]), "+f"(c[3])
        : "r"(a[0]), "r"(a[1]), "r"(a[2]), "r"(a[3]), "r"(b0), "r"(b1));
}
__device__ __forceinline__ void ldsm4(unsigned* d, unsigned addr) {
    asm volatile("ldmatrix.sync.aligned.m8n8.x4.shared.b16 {%0,%1,%2,%3}, [%4];"
                 : "=r"(d[0]), "=r"(d[1]), "=r"(d[2]), "=r"(d[3]) : "r"(addr));
}

__device__ __forceinline__ void g_stage(int c, unsigned buf, int row0, int tid) {
    const int k0 = c * KCH;
    #pragma unroll
    for (int j = 0; j < 2; ++j) {                // A: 512 x 16B
        const int idx = tid + 256 * j;
        const int half = idx >> 8;
        const int row = (idx & 255) >> 2, seg = idx & 3;
        const unsigned short* src = (half ? g_Al : g_Ah)
            + (size_t)(row0 + row) * D_DIM + k0 + seg * 8;
        cp16(buf + (half ? OFF_AL : OFF_AH) + row * (PITCH*2) + seg * 16, src);
    }
    #pragma unroll
    for (int j = 0; j < 8; ++j) {                // B: 2048 x 16B
        const int idx = tid + 256 * j;
        const int half = idx >> 10;
        const int nn = (idx & 1023) >> 2, seg = idx & 3;
        const unsigned short* src = (half ? g_Bl : g_Bh)
            + (size_t)nn * D_DIM + k0 + seg * 8;
        cp16(buf + (half ? OFF_BL : OFF_BH) + nn * (PITCH*2) + seg * 16, src);
    }
}

__global__ void __launch_bounds__(256) gemm_kernel(
    const int*   __restrict__ counts_w,
    const float* __restrict__ proj_b,
    const float* __restrict__ ln_w,
    const float* __restrict__ ln_b,
    const float* __restrict__ no_news,
    float*       __restrict__ out)
{
    extern __shared__ char sm[];                 // 3 x STAGE; epilogue reuses as h
    __shared__ float s_pb[O_DIM], s_lw[O_DIM], s_lb[O_DIM], s_nn[O_DIM];

    const int tid  = threadIdx.x;
    const int wid  = tid >> 5;
    const int lane = tid & 31;
    const int row0 = blockIdx.x * CTA_M;
    const bool i64 = counts_is_i64(counts_w);

    s_pb[tid] = proj_b[tid];
    s_lw[tid] = ln_w[tid];
    s_lb[tid] = ln_b[tid];
    s_nn[tid] = no_news[tid];

    const int warp_m = wid & 1;                  // 2 x 32 rows
    const int warp_n = wid >> 1;                 // 4 x 64 cols
    const int lq = lane & 3;
    const int lr = lane >> 2;

    float acc[2][8][4];
    #pragma unroll
    for (int mt = 0; mt < 2; ++mt)
        #pragma unroll
        for (int nt = 0; nt < 8; ++nt)
            #pragma unroll
            for (int j = 0; j < 4; ++j) acc[mt][nt][j] = 0.f;

    const unsigned smbase = smem_u32(sm);

    // ldmatrix per-lane address components (byte offsets, pitch 80B)
    const unsigned a_lane = (unsigned)((lane & 15) * 80 + (lane >> 4) * 16);
    const unsigned b_lane = (unsigned)((((lane >> 4) & 1) * 8 + (lane & 7)) * 80
                                       + ((lane >> 3) & 1) * 16);
    unsigned aoffH[2], aoffL[2];
    #pragma unroll
    for (int mt = 0; mt < 2; ++mt) {
        const unsigned r = (unsigned)((warp_m * 32 + mt * 16) * 80) + a_lane;
        aoffH[mt] = OFF_AH + r;
        aoffL[mt] = OFF_AL + r;
    }
    unsigned boffH[4], boffL[4];
    #pragma unroll
    for (int p = 0; p < 4; ++p) {
        const unsigned r = (unsigned)((warp_n * 64 + p * 16) * 80) + b_lane;
        boffH[p] = OFF_BH + r;
        boffL[p] = OFF_BL + r;
    }

    g_stage(0, smbase, row0, tid);
    asm volatile("cp.async.commit_group;" ::: "memory");
    g_stage(1, smbase + STAGE, row0, tid);
    asm volatile("cp.async.commit_group;" ::: "memory");

    #pragma unroll 1
    for (int c = 0; c < NCH; ++c) {
        asm volatile("cp.async.wait_group 1;" ::: "memory");
        __syncthreads();

        if (c + 2 < NCH)
            g_stage(c + 2, smbase + ((c + 2) % 3) * STAGE, row0, tid);
        asm volatile("cp.async.commit_group;" ::: "memory");

        const unsigned buf = smbase + (c % 3) * STAGE;
        #pragma unroll
        for (int ks = 0; ks < 2; ++ks) {
            const unsigned ko = ks * 32;
            unsigned ah[2][4], al[2][4];
            #pragma unroll
            for (int mt = 0; mt < 2; ++mt) {
                ldsm4(ah[mt], buf + aoffH[mt] + ko);
                ldsm4(al[mt], buf + aoffL[mt] + ko);
            }
            #pragma unroll
            for (int p = 0; p < 4; ++p) {
                unsigned bh[4], bl[4];
                ldsm4(bh, buf + boffH[p] + ko);
                ldsm4(bl, buf + boffL[p] + ko);
                #pragma unroll
                for (int s = 0; s < 2; ++s) {     // nt = 2p+s
                    const int nt = 2 * p + s;
                    const unsigned h0 = bh[2*s], h1 = bh[2*s+1];
                    const unsigned l0 = bl[2*s], l1 = bl[2*s+1];
                    #pragma unroll
                    for (int mt = 0; mt < 2; ++mt) {
                        mma16816(acc[mt][nt], ah[mt], h0, h1);
                        mma16816(acc[mt][nt], ah[mt], l0, l1);
                        mma16816(acc[mt][nt], al[mt], h0, h1);
                    }
                }
            }
        }
    }

    // ---- park h tile (+bias) in smem, then LN + GELU + no_news ----
    __syncthreads();
    float* h = reinterpret_cast<float*>(sm);     // [64][HPITCH]
    #pragma unroll
    for (int mt = 0; mt < 2; ++mt) {
        const int r = warp_m * 32 + mt * 16 + lr;
        #pragma unroll
        for (int nt = 0; nt < 8; ++nt) {
            const int cb = warp_n * 64 + nt * 8 + lq * 2;
            h[r * HPITCH + cb]           = acc[mt][nt][0] + s_pb[cb];
            h[r * HPITCH + cb + 1]       = acc[mt][nt][1] + s_pb[cb + 1];
            h[(r + 8) * HPITCH + cb]     = acc[mt][nt][2] + s_pb[cb];
            h[(r + 8) * HPITCH + cb + 1] = acc[mt][nt][3] + s_pb[cb + 1];
        }
    }
    __syncthreads();

    #pragma unroll 1
    for (int i = 0; i < 8; ++i) {
        const int r = wid * 8 + i;
        const int n_row = row0 + r;
        const float4 x0 = *reinterpret_cast<const float4*>(&h[r * HPITCH + lane * 8]);
        const float4 x1 = *reinterpret_cast<const float4*>(&h[r * HPITCH + lane * 8 + 4]);
        float v[8] = {x0.x, x0.y, x0.z, x0.w, x1.x, x1.y, x1.z, x1.w};

        float s = 0.f;
        #pragma unroll
        for (int j = 0; j < 8; ++j) s += v[j];
        #pragma unroll
        for (int o = 16; o > 0; o >>= 1) s += __shfl_xor_sync(0xffffffffu, s, o);
        const float mu = s * (1.f / O_DIM);

        float sq = 0.f;
        #pragma unroll
        for (int j = 0; j < 8; ++j) { const float d = v[j] - mu; sq += d * d; }
        #pragma unroll
        for (int o = 16; o > 0; o >>= 1) sq += __shfl_xor_sync(0xffffffffu, sq, o);
        const float inv = rsqrtf(sq * (1.f / O_DIM) + LN_EPS);

        const int cnt = load_count(counts_w, i64, n_row);
        float res[8];
        if (cnt > 0) {
            #pragma unroll
            for (int j = 0; j < 8; ++j) {
                const int col = lane * 8 + j;
                const float x = (v[j] - mu) * inv * s_lw[col] + s_lb[col];
                res[j] = 0.5f * x * (1.f + erff(x * 0.70710678118654752f));
            }
        } else {
            #pragma unroll
            for (int j = 0; j < 8; ++j) res[j] = s_nn[lane * 8 + j];
        }
        float4* o4 = reinterpret_cast<float4*>(out + (size_t)n_row * O_DIM + lane * 8);
        o4[0] = make_float4(res[0], res[1], res[2], res[3]);
        o4[1] = make_float4(res[4], res[5], res[6], res[7]);
    }
}

// ---------------------------------------------------------------------------
extern "C" void kernel_launch(void* const* d_in, const int* in_sizes, int n_in,
                              void* d_out, int out_size)
{
    const float* articles = (const float*)d_in[0];
    const int*   counts_w = (const int*)d_in[1];
    const float* attn_w   = (const float*)d_in[2];
    const float* attn_b   = (const float*)d_in[3];
    const float* proj_w   = (const float*)d_in[4];
    const float* proj_b   = (const float*)d_in[5];
    const float* ln_w     = (const float*)d_in[6];
    const float* ln_b     = (const float*)d_in[7];
    const float* no_news  = (const float*)d_in[8];
    float* out = (float*)d_out;

    const int smemG = 3 * STAGE;                            // 153600 B
    cudaFuncSetAttribute(gemm_kernel, cudaFuncAttributeMaxDynamicSharedMemorySize, smemG);

    prep_w_kernel<<<dim3(D_DIM / 32, O_DIM / 32), 256>>>(proj_w);
    pool_kernel<<<N_ROWS, 256>>>(articles, counts_w, attn_w, attn_b);
    gemm_kernel<<<G_TILES, 256, smemG>>>(counts_w, proj_b, ln_w, ln_b, no_news, out);
}

// round 14
// speedup vs baseline: 1.2546x; 1.2546x over previous
#include <cuda_runtime.h>
#include <cuda_bf16.h>
#include <math.h>

static constexpr int N_ROWS = 8192;
static constexpr int A_ART  = 32;
static constexpr int D_DIM  = 768;
static constexpr int O_DIM  = 256;
static constexpr float LN_EPS = 1e-5f;

// ---------------- GEMM geometry --------------------------------------------
static constexpr int CTA_M = 64;                    // rows per CTA
static constexpr int G_TILES = N_ROWS / CTA_M;      // 128 CTAs
static constexpr int KCH = 32;                      // k per chunk
static constexpr int NCH = D_DIM / KCH;             // 24 chunks
static constexpr int PITCH = 40;                    // bf16 per smem row (20 words)
static constexpr int A_SZ = CTA_M * PITCH * 2;      // 5120 B  per split
static constexpr int B_SZ = O_DIM * PITCH * 2;      // 20480 B per split
static constexpr int OFF_AH = 0;
static constexpr int OFF_AL = A_SZ;                 // 5120
static constexpr int OFF_BH = 2 * A_SZ;             // 10240
static constexpr int OFF_BL = 2 * A_SZ + B_SZ;      // 30720
static constexpr int STAGE  = 2 * (A_SZ + B_SZ);    // 51200
static constexpr int HPITCH = 260;                  // f32 epilogue tile pitch

static constexpr int NST = 16;                      // staged articles (49.2KB -> 4 CTAs/SM)

// bf16 hi/lo operand planes (zero-init; cnt==0 rows never written -> bias-only h, masked)
__device__ unsigned short g_Ah[(size_t)N_ROWS * D_DIM];
__device__ unsigned short g_Al[(size_t)N_ROWS * D_DIM];
__device__ unsigned short g_Bh[(size_t)O_DIM * D_DIM];   // [n][k]
__device__ unsigned short g_Bl[(size_t)O_DIM * D_DIM];

// ---------------------------------------------------------------------------
__device__ __forceinline__ bool counts_is_i64(const int* __restrict__ cw) {
    bool i64 = true;
    #pragma unroll
    for (int i = 0; i < 32; ++i)
        if (cw[2 * i + 1] != 0) i64 = false;
    return i64;
}
__device__ __forceinline__ int load_count(const int* __restrict__ cw, bool i64, int n) {
    return i64 ? cw[2 * n] : cw[n];
}
__device__ __forceinline__ unsigned smem_u32(const void* p) {
    unsigned a;
    asm("{ .reg .u64 t; cvta.to.shared.u64 t, %1; cvt.u32.u64 %0, t; }"
        : "=r"(a) : "l"(p));
    return a;
}
__device__ __forceinline__ void cp16(unsigned dst, const void* src) {
    asm volatile("cp.async.cg.shared.global [%0], [%1], 16;" :: "r"(dst), "l"(src));
}
__device__ __forceinline__ void bf16_split(float x, unsigned short& h, unsigned short& l) {
    const __nv_bfloat16 hb = __float2bfloat16(x);
    h = __bfloat16_as_ushort(hb);
    l = __bfloat16_as_ushort(__float2bfloat16(x - __bfloat162float(hb)));
}

// ---------------------------------------------------------------------------
// Weight prep: tiled 32x32 transpose, grid (24, 8).
// ---------------------------------------------------------------------------
__global__ void __launch_bounds__(256) prep_w_kernel(const float* __restrict__ proj_w) {
    __shared__ float t[32][33];
    const int k0 = blockIdx.x * 32;
    const int n0 = blockIdx.y * 32;
    const int tid = threadIdx.x;
    const int lr = tid >> 5;          // 0..7
    const int lc = tid & 31;
    #pragma unroll
    for (int j = 0; j < 4; ++j)
        t[lr + 8 * j][lc] = proj_w[(size_t)(k0 + lr + 8 * j) * O_DIM + n0 + lc];
    __syncthreads();
    const int n  = tid >> 3;          // 0..31
    const int kq = tid & 7;           // 4 k each
    unsigned short hs[4], ls[4];
    #pragma unroll
    for (int i = 0; i < 4; ++i)
        bf16_split(t[kq * 4 + i][n], hs[i], ls[i]);
    const size_t base = (size_t)(n0 + n) * D_DIM + k0 + kq * 4;
    *reinterpret_cast<uint2*>(&g_Bh[base]) =
        make_uint2(hs[0] | (hs[1] << 16), hs[2] | (hs[3] << 16));
    *reinterpret_cast<uint2*>(&g_Bl[base]) =
        make_uint2(ls[0] | (ls[1] << 16), ls[2] | (ls[3] << 16));
}

// ---------------------------------------------------------------------------
// Kernel A: masked attention softmax pooling. Stage first NST=16 articles in
// smem (49.2 KB -> 4 CTAs/SM); overflow articles scored from GMEM and
// re-read L2-hot (same-CTA window) in the pool phase. attn_w via __ldg.
// ---------------------------------------------------------------------------
__global__ void __launch_bounds__(256, 4) pool_kernel(
    const float* __restrict__ articles,
    const int*   __restrict__ counts_w,
    const float* __restrict__ attn_w,
    const float* __restrict__ attn_b)
{
    extern __shared__ float s_art[];          // [NST][768]
    __shared__ float s_scores[A_ART];
    __shared__ float s_wt[A_ART];

    const bool i64 = counts_is_i64(counts_w);
    const int n = blockIdx.x;
    const int cnt = load_count(counts_w, i64, n);
    if (cnt <= 0) return;                     // gemm epilogue writes no_news

    const int tid  = threadIdx.x;
    const int wid  = tid >> 5;
    const int lane = tid & 31;
    const int nst = cnt < NST ? cnt : NST;

    const float* src = articles + (size_t)n * A_ART * D_DIM;
    const unsigned sbase = smem_u32(s_art);
    const int nf4 = nst * (D_DIM / 4);
    for (int idx = tid; idx < nf4; idx += 256)
        cp16(sbase + idx * 16, src + idx * 4);
    asm volatile("cp.async.commit_group;" ::: "memory");
    asm volatile("cp.async.wait_group 0;" ::: "memory");
    __syncthreads();

    const float4* aw4 = reinterpret_cast<const float4*>(attn_w);
    const float4* src4 = reinterpret_cast<const float4*>(src);

    // scores: warp per article; staged from smem, overflow from gmem
    for (int a = wid; a < cnt; a += 8) {
        const float4* v4 = (a < NST)
            ? reinterpret_cast<const float4*>(s_art + a * D_DIM)
            : (src4 + a * (D_DIM / 4));
        float part = 0.f;
        #pragma unroll
        for (int j = 0; j < 6; ++j) {
            const int idx = lane + 32 * j;
            const float4 v = v4[idx];
            const float4 w = __ldg(aw4 + idx);
            part += v.x * w.x + v.y * w.y + v.z * w.z + v.w * w.w;
        }
        #pragma unroll
        for (int o = 16; o > 0; o >>= 1)
            part += __shfl_xor_sync(0xffffffffu, part, o);
        if (lane == 0) s_scores[a] = part;
    }
    __syncthreads();

    if (wid == 0) {
        const float b = attn_b[0];
        float s = (lane < cnt) ? (s_scores[lane] + b) : -3.0e38f;
        float m = s;
        #pragma unroll
        for (int o = 16; o > 0; o >>= 1)
            m = fmaxf(m, __shfl_xor_sync(0xffffffffu, m, o));
        float e = (lane < cnt) ? expf(s - m) : 0.f;
        float sum = e;
        #pragma unroll
        for (int o = 16; o > 0; o >>= 1)
            sum += __shfl_xor_sync(0xffffffffu, sum, o);
        if (lane < cnt) s_wt[lane] = e / sum;
    }
    __syncthreads();

    if (tid < D_DIM / 4) {
        float4 acc = make_float4(0.f, 0.f, 0.f, 0.f);
        for (int a = 0; a < nst; ++a) {
            const float wa = s_wt[a];
            const float4 v = reinterpret_cast<const float4*>(s_art + a * D_DIM)[tid];
            acc.x = fmaf(wa, v.x, acc.x);
            acc.y = fmaf(wa, v.y, acc.y);
            acc.z = fmaf(wa, v.z, acc.z);
            acc.w = fmaf(wa, v.w, acc.w);
        }
        for (int a = NST; a < cnt; ++a) {     // overflow: L2-hot re-read
            const float wa = s_wt[a];
            const float4 v = src4[a * (D_DIM / 4) + tid];
            acc.x = fmaf(wa, v.x, acc.x);
            acc.y = fmaf(wa, v.y, acc.y);
            acc.z = fmaf(wa, v.z, acc.z);
            acc.w = fmaf(wa, v.w, acc.w);
        }
        unsigned short hs[4], ls[4];
        bf16_split(acc.x, hs[0], ls[0]);
        bf16_split(acc.y, hs[1], ls[1]);
        bf16_split(acc.z, hs[2], ls[2]);
        bf16_split(acc.w, hs[3], ls[3]);
        const size_t base = (size_t)n * D_DIM + tid * 4;
        *reinterpret_cast<uint2*>(&g_Ah[base]) =
            make_uint2(hs[0] | (hs[1] << 16), hs[2] | (hs[3] << 16));
        *reinterpret_cast<uint2*>(&g_Al[base]) =
            make_uint2(ls[0] | (ls[1] << 16), ls[2] | (ls[3] << 16));
    }
}

// ---------------------------------------------------------------------------
// Kernel B: bf16x3 GEMM (mma.sync.m16n8k16) with ldmatrix fragment loads and
// a 3-stage cp.async pipeline (one __syncthreads per chunk).
// ---------------------------------------------------------------------------
__device__ __forceinline__ void mma16816(float* c, const unsigned* a,
                                         unsigned b0, unsigned b1) {
    asm volatile(
        "mma.sync.aligned.m16n8k16.row.col.f32.bf16.bf16.f32 "
        "{%0,%1,%2,%3}, {%4,%5,%6,%7}, {%8,%9}, {%0,%1,%2,%3};"
        : "+f"(c[0]), "+f"(c[1]), "+f"(c[2]), "+f"(c[3])
        : "r"(a[0]), "r"(a[1]), "r"(a[2]), "r"(a[3]), "r"(b0), "r"(b1));
}
__device__ __forceinline__ void ldsm4(unsigned* d, unsigned addr) {
    asm volatile("ldmatrix.sync.aligned.m8n8.x4.shared.b16 {%0,%1,%2,%3}, [%4];"
                 : "=r"(d[0]), "=r"(d[1]), "=r"(d[2]), "=r"(d[3]) : "r"(addr));
}

__device__ __forceinline__ void g_stage(int c, unsigned buf, int row0, int tid) {
    const int k0 = c * KCH;
    #pragma unroll
    for (int j = 0; j < 2; ++j) {                // A: 512 x 16B
        const int idx = tid + 256 * j;
        const int half = idx >> 8;
        const int row = (idx & 255) >> 2, seg = idx & 3;
        const unsigned short* src = (half ? g_Al : g_Ah)
            + (size_t)(row0 + row) * D_DIM + k0 + seg * 8;
        cp16(buf + (half ? OFF_AL : OFF_AH) + row * (PITCH*2) + seg * 16, src);
    }
    #pragma unroll
    for (int j = 0; j < 8; ++j) {                // B: 2048 x 16B
        const int idx = tid + 256 * j;
        const int half = idx >> 10;
        const int nn = (idx & 1023) >> 2, seg = idx & 3;
        const unsigned short* src = (half ? g_Bl : g_Bh)
            + (size_t)nn * D_DIM + k0 + seg * 8;
        cp16(buf + (half ? OFF_BL : OFF_BH) + nn * (PITCH*2) + seg * 16, src);
    }
}

__global__ void __launch_bounds__(256) gemm_kernel(
    const int*   __restrict__ counts_w,
    const float* __restrict__ proj_b,
    const float* __restrict__ ln_w,
    const float* __restrict__ ln_b,
    const float* __restrict__ no_news,
    float*       __restrict__ out)
{
    extern __shared__ char sm[];                 // 3 x STAGE; epilogue reuses as h
    __shared__ float s_pb[O_DIM], s_lw[O_DIM], s_lb[O_DIM], s_nn[O_DIM];

    const int tid  = threadIdx.x;
    const int wid  = tid >> 5;
    const int lane = tid & 31;
    const int row0 = blockIdx.x * CTA_M;
    const bool i64 = counts_is_i64(counts_w);

    s_pb[tid] = proj_b[tid];
    s_lw[tid] = ln_w[tid];
    s_lb[tid] = ln_b[tid];
    s_nn[tid] = no_news[tid];

    const int warp_m = wid & 1;                  // 2 x 32 rows
    const int warp_n = wid >> 1;                 // 4 x 64 cols
    const int lq = lane & 3;
    const int lr = lane >> 2;

    float acc[2][8][4];
    #pragma unroll
    for (int mt = 0; mt < 2; ++mt)
        #pragma unroll
        for (int nt = 0; nt < 8; ++nt)
            #pragma unroll
            for (int j = 0; j < 4; ++j) acc[mt][nt][j] = 0.f;

    const unsigned smbase = smem_u32(sm);

    // ldmatrix per-lane address components (byte offsets, pitch 80B)
    const unsigned a_lane = (unsigned)((lane & 15) * 80 + (lane >> 4) * 16);
    const unsigned b_lane = (unsigned)((((lane >> 4) & 1) * 8 + (lane & 7)) * 80
                                       + ((lane >> 3) & 1) * 16);
    unsigned aoffH[2], aoffL[2];
    #pragma unroll
    for (int mt = 0; mt < 2; ++mt) {
        const unsigned r = (unsigned)((warp_m * 32 + mt * 16) * 80) + a_lane;
        aoffH[mt] = OFF_AH + r;
        aoffL[mt] = OFF_AL + r;
    }
    unsigned boffH[4], boffL[4];
    #pragma unroll
    for (int p = 0; p < 4; ++p) {
        const unsigned r = (unsigned)((warp_n * 64 + p * 16) * 80) + b_lane;
        boffH[p] = OFF_BH + r;
        boffL[p] = OFF_BL + r;
    }

    g_stage(0, smbase, row0, tid);
    asm volatile("cp.async.commit_group;" ::: "memory");
    g_stage(1, smbase + STAGE, row0, tid);
    asm volatile("cp.async.commit_group;" ::: "memory");

    #pragma unroll 1
    for (int c = 0; c < NCH; ++c) {
        asm volatile("cp.async.wait_group 1;" ::: "memory");
        __syncthreads();

        if (c + 2 < NCH)
            g_stage(c + 2, smbase + ((c + 2) % 3) * STAGE, row0, tid);
        asm volatile("cp.async.commit_group;" ::: "memory");

        const unsigned buf = smbase + (c % 3) * STAGE;
        #pragma unroll
        for (int ks = 0; ks < 2; ++ks) {
            const unsigned ko = ks * 32;
            unsigned ah[2][4], al[2][4];
            #pragma unroll
            for (int mt = 0; mt < 2; ++mt) {
                ldsm4(ah[mt], buf + aoffH[mt] + ko);
                ldsm4(al[mt], buf + aoffL[mt] + ko);
            }
            #pragma unroll
            for (int p = 0; p < 4; ++p) {
                unsigned bh[4], bl[4];
                ldsm4(bh, buf + boffH[p] + ko);
                ldsm4(bl, buf + boffL[p] + ko);
                #pragma unroll
                for (int s = 0; s < 2; ++s) {     // nt = 2p+s
                    const int nt = 2 * p + s;
                    const unsigned h0 = bh[2*s], h1 = bh[2*s+1];
                    const unsigned l0 = bl[2*s], l1 = bl[2*s+1];
                    #pragma unroll
                    for (int mt = 0; mt < 2; ++mt) {
                        mma16816(acc[mt][nt], ah[mt], h0, h1);
                        mma16816(acc[mt][nt], ah[mt], l0, l1);
                        mma16816(acc[mt][nt], al[mt], h0, h1);
                    }
                }
            }
        }
    }

    // ---- park h tile (+bias) in smem, then LN + GELU + no_news ----
    __syncthreads();
    float* h = reinterpret_cast<float*>(sm);     // [64][HPITCH]
    #pragma unroll
    for (int mt = 0; mt < 2; ++mt) {
        const int r = warp_m * 32 + mt * 16 + lr;
        #pragma unroll
        for (int nt = 0; nt < 8; ++nt) {
            const int cb = warp_n * 64 + nt * 8 + lq * 2;
            h[r * HPITCH + cb]           = acc[mt][nt][0] + s_pb[cb];
            h[r * HPITCH + cb + 1]       = acc[mt][nt][1] + s_pb[cb + 1];
            h[(r + 8) * HPITCH + cb]     = acc[mt][nt][2] + s_pb[cb];
            h[(r + 8) * HPITCH + cb + 1] = acc[mt][nt][3] + s_pb[cb + 1];
        }
    }
    __syncthreads();

    #pragma unroll 1
    for (int i = 0; i < 8; ++i) {
        const int r = wid * 8 + i;
        const int n_row = row0 + r;
        const float4 x0 = *reinterpret_cast<const float4*>(&h[r * HPITCH + lane * 8]);
        const float4 x1 = *reinterpret_cast<const float4*>(&h[r * HPITCH + lane * 8 + 4]);
        float v[8] = {x0.x, x0.y, x0.z, x0.w, x1.x, x1.y, x1.z, x1.w};

        float s = 0.f;
        #pragma unroll
        for (int j = 0; j < 8; ++j) s += v[j];
        #pragma unroll
        for (int o = 16; o > 0; o >>= 1) s += __shfl_xor_sync(0xffffffffu, s, o);
        const float mu = s * (1.f / O_DIM);

        float sq = 0.f;
        #pragma unroll
        for (int j = 0; j < 8; ++j) { const float d = v[j] - mu; sq += d * d; }
        #pragma unroll
        for (int o = 16; o > 0; o >>= 1) sq += __shfl_xor_sync(0xffffffffu, sq, o);
        const float inv = rsqrtf(sq * (1.f / O_DIM) + LN_EPS);

        const int cnt = load_count(counts_w, i64, n_row);
        float res[8];
        if (cnt > 0) {
            #pragma unroll
            for (int j = 0; j < 8; ++j) {
                const int col = lane * 8 + j;
                const float x = (v[j] - mu) * inv * s_lw[col] + s_lb[col];
                res[j] = 0.5f * x * (1.f + erff(x * 0.70710678118654752f));
            }
        } else {
            #pragma unroll
            for (int j = 0; j < 8; ++j) res[j] = s_nn[lane * 8 + j];
        }
        float4* o4 = reinterpret_cast<float4*>(out + (size_t)n_row * O_DIM + lane * 8);
        o4[0] = make_float4(res[0], res[1], res[2], res[3]);
        o4[1] = make_float4(res[4], res[5], res[6], res[7]);
    }
}

// ---------------------------------------------------------------------------
extern "C" void kernel_launch(void* const* d_in, const int* in_sizes, int n_in,
                              void* d_out, int out_size)
{
    const float* articles = (const float*)d_in[0];
    const int*   counts_w = (const int*)d_in[1];
    const float* attn_w   = (const float*)d_in[2];
    const float* attn_b   = (const float*)d_in[3];
    const float* proj_w   = (const float*)d_in[4];
    const float* proj_b   = (const float*)d_in[5];
    const float* ln_w     = (const float*)d_in[6];
    const float* ln_b     = (const float*)d_in[7];
    const float* no_news  = (const float*)d_in[8];
    float* out = (float*)d_out;

    const int smemA = NST * D_DIM * (int)sizeof(float);     // 49152 B -> 4 CTAs/SM
    const int smemG = 3 * STAGE;                            // 153600 B
    cudaFuncSetAttribute(pool_kernel, cudaFuncAttributeMaxDynamicSharedMemorySize, smemA);
    cudaFuncSetAttribute(gemm_kernel, cudaFuncAttributeMaxDynamicSharedMemorySize, smemG);

    prep_w_kernel<<<dim3(D_DIM / 32, O_DIM / 32), 256>>>(proj_w);
    pool_kernel<<<N_ROWS, 256, smemA>>>(articles, counts_w, attn_w, attn_b);
    gemm_kernel<<<G_TILES, 256, smemG>>>(counts_w, proj_b, ln_w, ln_b, no_news, out);
}

// round 15
// speedup vs baseline: 1.3335x; 1.0629x over previous
#include <cuda_runtime.h>
#include <cuda_bf16.h>
#include <math.h>

static constexpr int N_ROWS = 8192;
static constexpr int A_ART  = 32;
static constexpr int D_DIM  = 768;
static constexpr int O_DIM  = 256;
static constexpr float LN_EPS = 1e-5f;

// ---------------- GEMM geometry --------------------------------------------
static constexpr int CTA_M = 64;                    // rows per CTA
static constexpr int G_TILES = N_ROWS / CTA_M;      // 128 CTAs
static constexpr int KCH = 32;                      // k per chunk
static constexpr int NCH = D_DIM / KCH;             // 24 chunks
static constexpr int PITCH = 40;                    // bf16 per smem row (20 words)
static constexpr int A_SZ = CTA_M * PITCH * 2;      // 5120 B  per split
static constexpr int B_SZ = O_DIM * PITCH * 2;      // 20480 B per split
static constexpr int OFF_AH = 0;
static constexpr int OFF_AL = A_SZ;                 // 5120
static constexpr int OFF_BH = 2 * A_SZ;             // 10240
static constexpr int OFF_BL = 2 * A_SZ + B_SZ;      // 30720
static constexpr int STAGE  = 2 * (A_SZ + B_SZ);    // 51200
static constexpr int HPITCH = 260;                  // f32 epilogue tile pitch

static constexpr int NST = 16;                      // staged articles (49.2KB)
static constexpr int PREP_TILES = (D_DIM / 32) * (O_DIM / 32);   // 192

// bf16 hi/lo operand planes (zero-init; cnt==0 rows never written -> bias-only h, masked)
__device__ unsigned short g_Ah[(size_t)N_ROWS * D_DIM];
__device__ unsigned short g_Al[(size_t)N_ROWS * D_DIM];
__device__ unsigned short g_Bh[(size_t)O_DIM * D_DIM];   // [n][k]
__device__ unsigned short g_Bl[(size_t)O_DIM * D_DIM];

// ---------------------------------------------------------------------------
__device__ __forceinline__ bool counts_is_i64(const int* __restrict__ cw) {
    bool i64 = true;
    #pragma unroll
    for (int i = 0; i < 32; ++i)
        if (cw[2 * i + 1] != 0) i64 = false;
    return i64;
}
__device__ __forceinline__ int load_count(const int* __restrict__ cw, bool i64, int n) {
    return i64 ? cw[2 * n] : cw[n];
}
__device__ __forceinline__ unsigned smem_u32(const void* p) {
    unsigned a;
    asm("{ .reg .u64 t; cvta.to.shared.u64 t, %1; cvt.u32.u64 %0, t; }"
        : "=r"(a) : "l"(p));
    return a;
}
__device__ __forceinline__ void cp16(unsigned dst, const void* src) {
    asm volatile("cp.async.cg.shared.global [%0], [%1], 16;" :: "r"(dst), "l"(src));
}
__device__ __forceinline__ void bf16_split(float x, unsigned short& h, unsigned short& l) {
    const __nv_bfloat16 hb = __float2bfloat16(x);
    h = __bfloat16_as_ushort(hb);
    l = __bfloat16_as_ushort(__float2bfloat16(x - __bfloat162float(hb)));
}

// ---------------------------------------------------------------------------
// Kernel A: masked attention softmax pooling + folded weight prep.
// cp.async burst for first NST articles; overflow articles (>=NST) scored
// from GMEM WHILE the burst flies (hides the wait); staged scored from smem.
// First PREP_TILES CTAs also transpose proj_w into Bh/Bl after burst issue.
// ---------------------------------------------------------------------------
__global__ void __launch_bounds__(256, 4) pool_kernel(
    const float* __restrict__ articles,
    const int*   __restrict__ counts_w,
    const float* __restrict__ attn_w,
    const float* __restrict__ attn_b,
    const float* __restrict__ proj_w)
{
    extern __shared__ float s_art[];          // [NST][768]
    __shared__ float s_scores[A_ART];
    __shared__ float s_wt[A_ART];
    __shared__ float s_t[32][33];             // prep transpose scratch

    const bool i64 = counts_is_i64(counts_w);
    const int n = blockIdx.x;
    const int cnt = load_count(counts_w, i64, n);

    const int tid  = threadIdx.x;
    const int wid  = tid >> 5;
    const int lane = tid & 31;
    const int nst = cnt < NST ? cnt : NST;

    const float* src = articles + (size_t)n * A_ART * D_DIM;
    const unsigned sbase = smem_u32(s_art);

    // ---- issue cp.async burst for staged articles (no wait yet) ----
    if (cnt > 0) {
        const int nf4 = nst * (D_DIM / 4);
        for (int idx = tid; idx < nf4; idx += 256)
            cp16(sbase + idx * 16, src + idx * 4);
    }
    asm volatile("cp.async.commit_group;" ::: "memory");

    // ---- folded weight prep (first PREP_TILES CTAs), overlaps burst ----
    if (n < PREP_TILES) {
        const int k0 = (n % (D_DIM / 32)) * 32;
        const int n0 = (n / (D_DIM / 32)) * 32;
        const int lr = tid >> 5, lc = tid & 31;
        #pragma unroll
        for (int j = 0; j < 4; ++j)
            s_t[lr + 8 * j][lc] = proj_w[(size_t)(k0 + lr + 8 * j) * O_DIM + n0 + lc];
        __syncthreads();
        const int nn = tid >> 3;
        const int kq = tid & 7;
        unsigned short hs[4], ls[4];
        #pragma unroll
        for (int i = 0; i < 4; ++i)
            bf16_split(s_t[kq * 4 + i][nn], hs[i], ls[i]);
        const size_t base = (size_t)(n0 + nn) * D_DIM + k0 + kq * 4;
        *reinterpret_cast<uint2*>(&g_Bh[base]) =
            make_uint2(hs[0] | (hs[1] << 16), hs[2] | (hs[3] << 16));
        *reinterpret_cast<uint2*>(&g_Bl[base]) =
            make_uint2(ls[0] | (ls[1] << 16), ls[2] | (ls[3] << 16));
    }
    if (cnt <= 0) return;                     // gemm epilogue writes no_news

    const float4* aw4 = reinterpret_cast<const float4*>(attn_w);
    const float4* src4 = reinterpret_cast<const float4*>(src);

    // ---- score OVERFLOW articles from GMEM while the burst flies ----
    for (int a = NST + wid; a < cnt; a += 8) {
        const float4* v4 = src4 + a * (D_DIM / 4);
        float part = 0.f;
        #pragma unroll
        for (int j = 0; j < 6; ++j) {
            const int idx = lane + 32 * j;
            const float4 v = v4[idx];
            const float4 w = __ldg(aw4 + idx);
            part += v.x * w.x + v.y * w.y + v.z * w.z + v.w * w.w;
        }
        #pragma unroll
        for (int o = 16; o > 0; o >>= 1)
            part += __shfl_xor_sync(0xffffffffu, part, o);
        if (lane == 0) s_scores[a] = part;
    }

    // ---- burst done by now; score staged articles from smem ----
    asm volatile("cp.async.wait_group 0;" ::: "memory");
    __syncthreads();

    for (int a = wid; a < nst; a += 8) {
        const float4* v4 = reinterpret_cast<const float4*>(s_art + a * D_DIM);
        float part = 0.f;
        #pragma unroll
        for (int j = 0; j < 6; ++j) {
            const int idx = lane + 32 * j;
            const float4 v = v4[idx];
            const float4 w = __ldg(aw4 + idx);
            part += v.x * w.x + v.y * w.y + v.z * w.z + v.w * w.w;
        }
        #pragma unroll
        for (int o = 16; o > 0; o >>= 1)
            part += __shfl_xor_sync(0xffffffffu, part, o);
        if (lane == 0) s_scores[a] = part;
    }
    __syncthreads();

    // ---- softmax over valid articles (warp 0) ----
    if (wid == 0) {
        const float b = attn_b[0];
        float s = (lane < cnt) ? (s_scores[lane] + b) : -3.0e38f;
        float m = s;
        #pragma unroll
        for (int o = 16; o > 0; o >>= 1)
            m = fmaxf(m, __shfl_xor_sync(0xffffffffu, m, o));
        float e = (lane < cnt) ? expf(s - m) : 0.f;
        float sum = e;
        #pragma unroll
        for (int o = 16; o > 0; o >>= 1)
            sum += __shfl_xor_sync(0xffffffffu, sum, o);
        if (lane < cnt) s_wt[lane] = e / sum;
    }
    __syncthreads();

    // ---- pool: staged from smem, overflow from gmem (L2-hot) ----
    if (tid < D_DIM / 4) {
        float4 acc = make_float4(0.f, 0.f, 0.f, 0.f);
        for (int a = 0; a < nst; ++a) {
            const float wa = s_wt[a];
            const float4 v = reinterpret_cast<const float4*>(s_art + a * D_DIM)[tid];
            acc.x = fmaf(wa, v.x, acc.x);
            acc.y = fmaf(wa, v.y, acc.y);
            acc.z = fmaf(wa, v.z, acc.z);
            acc.w = fmaf(wa, v.w, acc.w);
        }
        for (int a = NST; a < cnt; ++a) {
            const float wa = s_wt[a];
            const float4 v = src4[a * (D_DIM / 4) + tid];
            acc.x = fmaf(wa, v.x, acc.x);
            acc.y = fmaf(wa, v.y, acc.y);
            acc.z = fmaf(wa, v.z, acc.z);
            acc.w = fmaf(wa, v.w, acc.w);
        }
        unsigned short hs[4], ls[4];
        bf16_split(acc.x, hs[0], ls[0]);
        bf16_split(acc.y, hs[1], ls[1]);
        bf16_split(acc.z, hs[2], ls[2]);
        bf16_split(acc.w, hs[3], ls[3]);
        const size_t base = (size_t)n * D_DIM + tid * 4;
        *reinterpret_cast<uint2*>(&g_Ah[base]) =
            make_uint2(hs[0] | (hs[1] << 16), hs[2] | (hs[3] << 16));
        *reinterpret_cast<uint2*>(&g_Al[base]) =
            make_uint2(ls[0] | (ls[1] << 16), ls[2] | (ls[3] << 16));
    }
}

// ---------------------------------------------------------------------------
// Kernel B: bf16x3 GEMM (mma.sync.m16n8k16) with ldmatrix fragment loads and
// a 3-stage cp.async pipeline (one __syncthreads per chunk).
// ---------------------------------------------------------------------------
__device__ __forceinline__ void mma16816(float* c, const unsigned* a,
                                         unsigned b0, unsigned b1) {
    asm volatile(
        "mma.sync.aligned.m16n8k16.row.col.f32.bf16.bf16.f32 "
        "{%0,%1,%2,%3}, {%4,%5,%6,%7}, {%8,%9}, {%0,%1,%2,%3};"
        : "+f"(c[0]), "+f"(c[1]), "+f"(c[2]), "+f"(c[3])
        : "r"(a[0]), "r"(a[1]), "r"(a[2]), "r"(a[3]), "r"(b0), "r"(b1));
}
__device__ __forceinline__ void ldsm4(unsigned* d, unsigned addr) {
    asm volatile("ldmatrix.sync.aligned.m8n8.x4.shared.b16 {%0,%1,%2,%3}, [%4];"
                 : "=r"(d[0]), "=r"(d[1]), "=r"(d[2]), "=r"(d[3]) : "r"(addr));
}

__device__ __forceinline__ void g_stage(int c, unsigned buf, int row0, int tid) {
    const int k0 = c * KCH;
    #pragma unroll
    for (int j = 0; j < 2; ++j) {                // A: 512 x 16B
        const int idx = tid + 256 * j;
        const int half = idx >> 8;
        const int row = (idx & 255) >> 2, seg = idx & 3;
        const unsigned short* src = (half ? g_Al : g_Ah)
            + (size_t)(row0 + row) * D_DIM + k0 + seg * 8;
        cp16(buf + (half ? OFF_AL : OFF_AH) + row * (PITCH*2) + seg * 16, src);
    }
    #pragma unroll
    for (int j = 0; j < 8; ++j) {                // B: 2048 x 16B
        const int idx = tid + 256 * j;
        const int half = idx >> 10;
        const int nn = (idx & 1023) >> 2, seg = idx & 3;
        const unsigned short* src = (half ? g_Bl : g_Bh)
            + (size_t)nn * D_DIM + k0 + seg * 8;
        cp16(buf + (half ? OFF_BL : OFF_BH) + nn * (PITCH*2) + seg * 16, src);
    }
}

__global__ void __launch_bounds__(256) gemm_kernel(
    const int*   __restrict__ counts_w,
    const float* __restrict__ proj_b,
    const float* __restrict__ ln_w,
    const float* __restrict__ ln_b,
    const float* __restrict__ no_news,
    float*       __restrict__ out)
{
    extern __shared__ char sm[];                 // 3 x STAGE; epilogue reuses as h
    __shared__ float s_pb[O_DIM], s_lw[O_DIM], s_lb[O_DIM], s_nn[O_DIM];

    const int tid  = threadIdx.x;
    const int wid  = tid >> 5;
    const int lane = tid & 31;
    const int row0 = blockIdx.x * CTA_M;
    const bool i64 = counts_is_i64(counts_w);

    s_pb[tid] = proj_b[tid];
    s_lw[tid] = ln_w[tid];
    s_lb[tid] = ln_b[tid];
    s_nn[tid] = no_news[tid];

    const int warp_m = wid & 1;                  // 2 x 32 rows
    const int warp_n = wid >> 1;                 // 4 x 64 cols
    const int lq = lane & 3;
    const int lr = lane >> 2;

    float acc[2][8][4];
    #pragma unroll
    for (int mt = 0; mt < 2; ++mt)
        #pragma unroll
        for (int nt = 0; nt < 8; ++nt)
            #pragma unroll
            for (int j = 0; j < 4; ++j) acc[mt][nt][j] = 0.f;

    const unsigned smbase = smem_u32(sm);

    // ldmatrix per-lane address components (byte offsets, pitch 80B)
    const unsigned a_lane = (unsigned)((lane & 15) * 80 + (lane >> 4) * 16);
    const unsigned b_lane = (unsigned)((((lane >> 4) & 1) * 8 + (lane & 7)) * 80
                                       + ((lane >> 3) & 1) * 16);
    unsigned aoffH[2], aoffL[2];
    #pragma unroll
    for (int mt = 0; mt < 2; ++mt) {
        const unsigned r = (unsigned)((warp_m * 32 + mt * 16) * 80) + a_lane;
        aoffH[mt] = OFF_AH + r;
        aoffL[mt] = OFF_AL + r;
    }
    unsigned boffH[4], boffL[4];
    #pragma unroll
    for (int p = 0; p < 4; ++p) {
        const unsigned r = (unsigned)((warp_n * 64 + p * 16) * 80) + b_lane;
        boffH[p] = OFF_BH + r;
        boffL[p] = OFF_BL + r;
    }

    g_stage(0, smbase, row0, tid);
    asm volatile("cp.async.commit_group;" ::: "memory");
    g_stage(1, smbase + STAGE, row0, tid);
    asm volatile("cp.async.commit_group;" ::: "memory");

    #pragma unroll 1
    for (int c = 0; c < NCH; ++c) {
        asm volatile("cp.async.wait_group 1;" ::: "memory");
        __syncthreads();

        if (c + 2 < NCH)
            g_stage(c + 2, smbase + ((c + 2) % 3) * STAGE, row0, tid);
        asm volatile("cp.async.commit_group;" ::: "memory");

        const unsigned buf = smbase + (c % 3) * STAGE;
        #pragma unroll
        for (int ks = 0; ks < 2; ++ks) {
            const unsigned ko = ks * 32;
            unsigned ah[2][4], al[2][4];
            #pragma unroll
            for (int mt = 0; mt < 2; ++mt) {
                ldsm4(ah[mt], buf + aoffH[mt] + ko);
                ldsm4(al[mt], buf + aoffL[mt] + ko);
            }
            #pragma unroll
            for (int p = 0; p < 4; ++p) {
                unsigned bh[4], bl[4];
                ldsm4(bh, buf + boffH[p] + ko);
                ldsm4(bl, buf + boffL[p] + ko);
                #pragma unroll
                for (int s = 0; s < 2; ++s) {     // nt = 2p+s
                    const int nt = 2 * p + s;
                    const unsigned h0 = bh[2*s], h1 = bh[2*s+1];
                    const unsigned l0 = bl[2*s], l1 = bl[2*s+1];
                    #pragma unroll
                    for (int mt = 0; mt < 2; ++mt) {
                        mma16816(acc[mt][nt], ah[mt], h0, h1);
                        mma16816(acc[mt][nt], ah[mt], l0, l1);
                        mma16816(acc[mt][nt], al[mt], h0, h1);
                    }
                }
            }
        }
    }

    // ---- park h tile (+bias) in smem, then LN + GELU + no_news ----
    __syncthreads();
    float* h = reinterpret_cast<float*>(sm);     // [64][HPITCH]
    #pragma unroll
    for (int mt = 0; mt < 2; ++mt) {
        const int r = warp_m * 32 + mt * 16 + lr;
        #pragma unroll
        for (int nt = 0; nt < 8; ++nt) {
            const int cb = warp_n * 64 + nt * 8 + lq * 2;
            h[r * HPITCH + cb]           = acc[mt][nt][0] + s_pb[cb];
            h[r * HPITCH + cb + 1]       = acc[mt][nt][1] + s_pb[cb + 1];
            h[(r + 8) * HPITCH + cb]     = acc[mt][nt][2] + s_pb[cb];
            h[(r + 8) * HPITCH + cb + 1] = acc[mt][nt][3] + s_pb[cb + 1];
        }
    }
    __syncthreads();

    #pragma unroll 1
    for (int i = 0; i < 8; ++i) {
        const int r = wid * 8 + i;
        const int n_row = row0 + r;
        const float4 x0 = *reinterpret_cast<const float4*>(&h[r * HPITCH + lane * 8]);
        const float4 x1 = *reinterpret_cast<const float4*>(&h[r * HPITCH + lane * 8 + 4]);
        float v[8] = {x0.x, x0.y, x0.z, x0.w, x1.x, x1.y, x1.z, x1.w};

        float s = 0.f;
        #pragma unroll
        for (int j = 0; j < 8; ++j) s += v[j];
        #pragma unroll
        for (int o = 16; o > 0; o >>= 1) s += __shfl_xor_sync(0xffffffffu, s, o);
        const float mu = s * (1.f / O_DIM);

        float sq = 0.f;
        #pragma unroll
        for (int j = 0; j < 8; ++j) { const float d = v[j] - mu; sq += d * d; }
        #pragma unroll
        for (int o = 16; o > 0; o >>= 1) sq += __shfl_xor_sync(0xffffffffu, sq, o);
        const float inv = rsqrtf(sq * (1.f / O_DIM) + LN_EPS);

        const int cnt = load_count(counts_w, i64, n_row);
        float res[8];
        if (cnt > 0) {
            #pragma unroll
            for (int j = 0; j < 8; ++j) {
                const int col = lane * 8 + j;
                const float x = (v[j] - mu) * inv * s_lw[col] + s_lb[col];
                res[j] = 0.5f * x * (1.f + erff(x * 0.70710678118654752f));
            }
        } else {
            #pragma unroll
            for (int j = 0; j < 8; ++j) res[j] = s_nn[lane * 8 + j];
        }
        float4* o4 = reinterpret_cast<float4*>(out + (size_t)n_row * O_DIM + lane * 8);
        o4[0] = make_float4(res[0], res[1], res[2], res[3]);
        o4[1] = make_float4(res[4], res[5], res[6], res[7]);
    }
}

// ---------------------------------------------------------------------------
extern "C" void kernel_launch(void* const* d_in, const int* in_sizes, int n_in,
                              void* d_out, int out_size)
{
    const float* articles = (const float*)d_in[0];
    const int*   counts_w = (const int*)d_in[1];
    const float* attn_w   = (const float*)d_in[2];
    const float* attn_b   = (const float*)d_in[3];
    const float* proj_w   = (const float*)d_in[4];
    const float* proj_b   = (const float*)d_in[5];
    const float* ln_w     = (const float*)d_in[6];
    const float* ln_b     = (const float*)d_in[7];
    const float* no_news  = (const float*)d_in[8];
    float* out = (float*)d_out;

    const int smemA = NST * D_DIM * (int)sizeof(float);     // 49152 B dynamic
    const int smemG = 3 * STAGE;                            // 153600 B
    cudaFuncSetAttribute(pool_kernel, cudaFuncAttributeMaxDynamicSharedMemorySize, smemA);
    cudaFuncSetAttribute(gemm_kernel, cudaFuncAttributeMaxDynamicSharedMemorySize, smemG);

    pool_kernel<<<N_ROWS, 256, smemA>>>(articles, counts_w, attn_w, attn_b, proj_w);
    gemm_kernel<<<G_TILES, 256, smemG>>>(counts_w, proj_b, ln_w, ln_b, no_news, out);
}